// round 17
// baseline (speedup 1.0000x reference)
#include <cuda_runtime.h>
#include <cuda_fp16.h>
#include <math.h>
#include <stdint.h>

// Problem constants
#define B_    4
#define T_    2048
#define C_    2048
#define NH_   16
#define NKV_  8
#define HD_   128
#define M_    (B_*T_)          // 8192
#define KVD_  (NKV_*HD_)       // 1024
#define QKVN  (C_ + 2*KVD_)    // 4096

// ---------------- scratch ----------------------------------------------------
__device__ __half g_wqkvh[(size_t)QKVN * C_];          // Wq|Wk|Wv fp16
__device__ __half g_worh[(size_t)C_ * C_];             // Wo fp16
__device__ __half g_qkvh[(size_t)M_ * QKVN];           // q/k (rope'd) fp16; V cols unused
__device__ __half g_vth[(size_t)B_ * NKV_ * HD_ * T_]; // V transposed fp16
__device__ __half g_oh[(size_t)M_ * C_];               // attention out fp16
__device__ float4 g_ropetab[(size_t)T_ * 32];          // (c1,s1,c2,s2) per (t, i1)

// ---------------- helpers ----------------------------------------------------
__device__ __forceinline__ void cp_async16(void* smem, const void* gmem) {
    uint32_t sa = (uint32_t)__cvta_generic_to_shared(smem);
    asm volatile("cp.async.cg.shared.global [%0], [%1], 16;\n" :: "r"(sa), "l"(gmem));
}
#define CP_COMMIT() asm volatile("cp.async.commit_group;\n" ::: "memory")
#define CP_WAIT(n)  asm volatile("cp.async.wait_group %0;\n" :: "n"(n) : "memory")

#define MMA_F16(d, a, b) \
    asm volatile("mma.sync.aligned.m16n8k16.row.col.f32.f16.f16.f32 " \
                 "{%0,%1,%2,%3}, {%4,%5,%6,%7}, {%8,%9}, {%0,%1,%2,%3};" \
                 : "+f"(d[0]), "+f"(d[1]), "+f"(d[2]), "+f"(d[3]) \
                 : "r"(a[0]), "r"(a[1]), "r"(a[2]), "r"(a[3]), "r"(b[0]), "r"(b[1]))

__device__ __forceinline__ void ldsm4(uint32_t* r, const void* p) {
    uint32_t a = (uint32_t)__cvta_generic_to_shared(p);
    asm volatile("ldmatrix.sync.aligned.m8n8.x4.shared.b16 {%0,%1,%2,%3}, [%4];"
                 : "=r"(r[0]), "=r"(r[1]), "=r"(r[2]), "=r"(r[3]) : "r"(a));
}

__device__ __forceinline__ float ex2f(float x) {     // raw exp2, schedulable
    float y;
    asm("ex2.approx.ftz.f32 %0, %1;" : "=f"(y) : "f"(x));
    return y;
}

__device__ __forceinline__ void store2(float* p, float a, float b) {
    *(float2*)p = make_float2(a, b);
}
__device__ __forceinline__ void store2(__half* p, float a, float b) {
    *(__half2*)p = __floats2half2_rn(a, b);
}

#define L2C_ 0.20762050593046f   // log2(10000)/64

// ---------------- prep: weight fp16 conversion + rope table (one launch) -----
#define NQ4 ((size_t)C_ * C_ / 4)
#define NK4 ((size_t)KVD_ * C_ / 4)
#define RW_THREADS ((2 * NQ4 + 2 * NK4) / 4)          // 655360
#define PREP_TOTAL (RW_THREADS + (size_t)T_ * 32)     // + 65536 ropetab items

__global__ void prep_kernel(const float* __restrict__ Wq, const float* __restrict__ Wk,
                            const float* __restrict__ Wv, const float* __restrict__ Wo,
                            float4* __restrict__ tab) {
    size_t tix = (size_t)blockIdx.x * blockDim.x + threadIdx.x;
    if (tix >= RW_THREADS) {
        size_t idx = tix - RW_THREADS;
        if (idx >= (size_t)T_ * 32) return;
        int t = (int)(idx >> 5), i = (int)(idx & 31);
        float inv1 = exp2f(-(float)i * L2C_);
        float inv2 = exp2f(-(float)(i + 32) * L2C_);
        float s1, c1, s2, c2;
        sincosf((float)t * inv1, &s1, &c1);
        sincosf((float)t * inv2, &s2, &c2);
        tab[idx] = make_float4(c1, s1, c2, s2);
        return;
    }
    size_t j = tix * 4;
    const float4* src; __half* dst; size_t off;
    if (j < NQ4)                 { src = (const float4*)Wq; dst = g_wqkvh; off = j; }
    else if (j < NQ4 + NK4)      { src = (const float4*)Wk; dst = g_wqkvh + (size_t)C_ * C_; off = j - NQ4; }
    else if (j < NQ4 + 2*NK4)    { src = (const float4*)Wv; dst = g_wqkvh + (size_t)(C_ + KVD_) * C_; off = j - NQ4 - NK4; }
    else                         { src = (const float4*)Wo; dst = g_worh;  off = j - NQ4 - 2*NK4; }
#pragma unroll
    for (int i = 0; i < 4; i++) {
        float4 v = src[off + i];
        *(__half2*)(dst + (off + i) * 4)     = __floats2half2_rn(v.x, v.y);
        *(__half2*)(dst + (off + i) * 4 + 2) = __floats2half2_rn(v.z, v.w);
    }
}

// ---------------- fp16 tensor-core GEMM: C[M,N] = A[M,K] * B[N,K]^T ----------
// Single barrier per K-iter. KCH = K-chunk (32 or 64).
// AT=float (KCH=32 only): A converted fp32->fp16 via register prefetch + STS.
// FUSE_EPI: bx<24 -> rope epilogue; bx>=24 -> transposed V store.
#define HBM 128
#define HBN 128
#define RSTG 136  // rope stage stride (halves)
#define RSTV 130  // vtrans stage stride (halves)
#define GEMM_SMEM(KCH) (2 * (HBM * ((KCH) + 8) + HBN * ((KCH) + 8)) * 2)

template <typename AT, typename OT, bool FUSE_EPI, int KCH>
__global__ void __launch_bounds__(256, 2) gemm_h(const AT* __restrict__ A,
                                                 const __half* __restrict__ Bm,
                                                 OT* __restrict__ Cm,
                                                 __half* __restrict__ Vt,
                                                 const float4* __restrict__ ropetab,
                                                 int M, int N, int K) {
    constexpr int HSTRt = KCH + 8;
    constexpr int CPR = KCH / 8;                  // 16B chunks per row
    constexpr int LIT = (HBM * CPR) / 256;        // loader iterations
    extern __shared__ __half hs[];
    __half* As = hs;
    __half* Bs = hs + 2 * HBM * HSTRt;

    const int tid = threadIdx.x;
    const int wid = tid >> 5;
    const int lane = tid & 31;
    const int warp_m = wid >> 2;
    const int warp_n = wid & 3;
    const int g = lane >> 2;
    const int t = lane & 3;

    const int rowA  = lane & 15;
    const int koffA = (lane >> 4) * 8;
    const int rowB  = (lane & 7) + ((lane >> 4) << 3);
    const int koffB = ((lane >> 3) & 1) * 8;

    const AT* Ag = A + (size_t)blockIdx.y * HBM * K;
    const __half* Bg = Bm + (size_t)blockIdx.x * HBN * K;

    float c[4][4][4];
#pragma unroll
    for (int mt = 0; mt < 4; mt++)
#pragma unroll
        for (int nt = 0; nt < 4; nt++)
#pragma unroll
            for (int r = 0; r < 4; r++) c[mt][nt][r] = 0.f;

    auto load_B = [&](int it, int buf) {
        int k0 = it * KCH;
        __half* bs = Bs + buf * HBN * HSTRt;
#pragma unroll
        for (int i = 0; i < LIT; i++) {
            int idx = i * 256 + tid;
            int r = idx / CPR, cc = idx % CPR;
            cp_async16(bs + r * HSTRt + cc * 8, Bg + (size_t)r * K + k0 + cc * 8);
        }
    };
    auto load_A_async = [&](int it, int buf) {   // fp16 A path
        int k0 = it * KCH;
        __half* as = As + buf * HBM * HSTRt;
#pragma unroll
        for (int i = 0; i < LIT; i++) {
            int idx = i * 256 + tid;
            int r = idx / CPR, cc = idx % CPR;
            cp_async16(as + r * HSTRt + cc * 8, (const __half*)Ag + (size_t)r * K + k0 + cc * 8);
        }
    };

    float4 ra[4];
    auto ldg_A = [&](int it) {                  // fp32 A path (KCH=32 only)
        int k0 = it * KCH;
#pragma unroll
        for (int i = 0; i < 2; i++) {
            int idx = i * 256 + tid;
            int r = idx >> 2, cc = idx & 3;
            const float* p = (const float*)Ag + (size_t)r * K + k0 + cc * 8;
            ra[2 * i]     = *(const float4*)p;
            ra[2 * i + 1] = *(const float4*)(p + 4);
        }
    };
    auto sts_A = [&](int buf) {
        __half* as = As + buf * HBM * HSTRt;
#pragma unroll
        for (int i = 0; i < 2; i++) {
            int idx = i * 256 + tid;
            int r = idx >> 2, cc = idx & 3;
            __half2 h0 = __floats2half2_rn(ra[2*i].x,   ra[2*i].y);
            __half2 h1 = __floats2half2_rn(ra[2*i].z,   ra[2*i].w);
            __half2 h2 = __floats2half2_rn(ra[2*i+1].x, ra[2*i+1].y);
            __half2 h3 = __floats2half2_rn(ra[2*i+1].z, ra[2*i+1].w);
            uint4 u;
            u.x = *(uint32_t*)&h0; u.y = *(uint32_t*)&h1;
            u.z = *(uint32_t*)&h2; u.w = *(uint32_t*)&h3;
            *(uint4*)(as + r * HSTRt + cc * 8) = u;
        }
    };

    constexpr bool A_F32 = (sizeof(AT) == 4);
    static_assert(!A_F32 || KCH == 32, "fp32-A requires KCH=32");
    const int NIT = K / KCH;

    if constexpr (A_F32) {
        ldg_A(0); sts_A(0);
        ldg_A(1);
        load_B(0, 0);
        CP_COMMIT();
    } else {
        load_A_async(0, 0);
        load_B(0, 0);
        CP_COMMIT();
    }

    for (int it = 0; it < NIT; ++it) {
        const int cur = it & 1;
        CP_WAIT(0);
        __syncthreads();
        if (it + 1 < NIT) {
            if constexpr (A_F32) {
                sts_A(cur ^ 1);
                if (it + 2 < NIT) ldg_A(it + 2);
                load_B(it + 1, cur ^ 1);
            } else {
                load_A_async(it + 1, cur ^ 1);
                load_B(it + 1, cur ^ 1);
            }
            CP_COMMIT();
        }

        const __half* as = As + cur * HBM * HSTRt;
        const __half* bs = Bs + cur * HBN * HSTRt;

#pragma unroll
        for (int kk = 0; kk < KCH; kk += 16) {
            uint32_t af[4][4], bf4[2][4];
#pragma unroll
            for (int mt = 0; mt < 4; mt++)
                ldsm4(af[mt], as + (warp_m * 64 + mt * 16 + rowA) * HSTRt + kk + koffA);
#pragma unroll
            for (int np = 0; np < 2; np++)
                ldsm4(bf4[np], bs + (warp_n * 32 + np * 16 + rowB) * HSTRt + kk + koffB);
#pragma unroll
            for (int mt = 0; mt < 4; mt++)
#pragma unroll
                for (int nt = 0; nt < 4; nt++)
                    MMA_F16(c[mt][nt], af[mt], (&bf4[nt >> 1][(nt & 1) * 2]));
        }
    }

    // ---------------- epilogue ----------------
    if (FUSE_EPI && (int)blockIdx.x < 24) {
        __syncthreads();
        __half* Cs = hs;                       // 128*136 = 17408 <= 20480 halves
#pragma unroll
        for (int mt = 0; mt < 4; mt++) {
#pragma unroll
            for (int nt = 0; nt < 4; nt++) {
                int row = warp_m * 64 + mt * 16 + g;
                int col = warp_n * 32 + nt * 8 + 2 * t;
                *(__half2*)(Cs + row * RSTG + col)       = __floats2half2_rn(c[mt][nt][0], c[mt][nt][1]);
                *(__half2*)(Cs + (row + 8) * RSTG + col) = __floats2half2_rn(c[mt][nt][2], c[mt][nt][3]);
            }
        }
        __syncthreads();
        const int rowg0 = blockIdx.y * HBM;
        __half* dstb = (__half*)Cm + (size_t)blockIdx.x * HBN;
#pragma unroll
        for (int i = 0; i < 16; i++) {
            int item = tid + i * 256;
            int r = item >> 5, d2i = item & 31, d2 = d2i * 2;
            int tg = (rowg0 + r) & (T_ - 1);
            float4 tb = ropetab[tg * 32 + d2i];
            __half2 lo = *(__half2*)(Cs + r * RSTG + d2);
            __half2 hi = *(__half2*)(Cs + r * RSTG + d2 + 64);
            float x1a = __low2float(lo), x1b = __high2float(lo);
            float x2a = __low2float(hi), x2b = __high2float(hi);
            __half* dst = dstb + (size_t)(rowg0 + r) * N;
            *(__half2*)(dst + d2)      = __floats2half2_rn(x1a * tb.x - x2a * tb.y,
                                                           x1b * tb.x - x2b * tb.y);
            *(__half2*)(dst + d2 + 64) = __floats2half2_rn(x2a * tb.z + x1a * tb.w,
                                                           x2b * tb.z + x1b * tb.w);
        }
    } else if (FUSE_EPI) {
        __syncthreads();
        __half* Cs = hs;                       // 128*130 = 16640 halves
#pragma unroll
        for (int mt = 0; mt < 4; mt++) {
#pragma unroll
            for (int nt = 0; nt < 4; nt++) {
                int row = warp_m * 64 + mt * 16 + g;
                int col = warp_n * 32 + nt * 8 + 2 * t;
                *(__half2*)(Cs + row * RSTV + col)       = __floats2half2_rn(c[mt][nt][0], c[mt][nt][1]);
                *(__half2*)(Cs + (row + 8) * RSTV + col) = __floats2half2_rn(c[mt][nt][2], c[mt][nt][3]);
            }
        }
        __syncthreads();
        const int kvh = (int)blockIdx.x - 24;
        const int rowg0 = blockIdx.y * HBM;
        const int b = rowg0 / T_;
        const int t0 = rowg0 & (T_ - 1);
        __half* dstb = Vt + ((size_t)(b * NKV_ + kvh) * HD_) * T_ + t0;
#pragma unroll
        for (int i = 0; i < 8; i++) {
            int item = tid + i * 256;
            int hd = item >> 4, tc = item & 15;
            __half tmp[8];
#pragma unroll
            for (int jj = 0; jj < 8; jj++)
                tmp[jj] = Cs[(tc * 8 + jj) * RSTV + hd];
            *(uint4*)(dstb + (size_t)hd * T_ + tc * 8) = *(uint4*)tmp;
        }
    } else {
        const int row_base = blockIdx.y * HBM + warp_m * 64;
        const int col_base = blockIdx.x * HBN + warp_n * 32;
#pragma unroll
        for (int mt = 0; mt < 4; mt++) {
#pragma unroll
            for (int nt = 0; nt < 4; nt++) {
                int row = row_base + mt * 16 + g;
                int col = col_base + nt * 8 + 2 * t;
                store2(Cm + (size_t)row * N + col,       c[mt][nt][0], c[mt][nt][1]);
                store2(Cm + (size_t)(row + 8) * N + col, c[mt][nt][2], c[mt][nt][3]);
            }
        }
    }
}

// ---------------- Flash attention: FA2, log2-domain softmax, deferred sums ---
#define ABM 128
#define ABN 64
#define AH_QST 136
#define AH_VST 72
#define AQ_HALVES (128 * AH_QST)
#define AK_HALVES (64 * AH_QST)
#define AV_HALVES (128 * AH_VST)
#define ATTH_SMEM_BYTES ((AQ_HALVES + 2 * AK_HALVES + 2 * AV_HALVES) * 2)  // 106496

__global__ void __launch_bounds__(256, 2) attn_h_kernel(const __half* __restrict__ QKVh,
                                                        const __half* __restrict__ Vth,
                                                        __half* __restrict__ Oh) {
    const int qt  = (int)gridDim.x - 1 - (int)blockIdx.x;
    const int h   = blockIdx.y;
    const int b   = blockIdx.z;
    const int kvh = h >> 1;

    extern __shared__ __half sh[];
    __half* Qs = sh;
    __half* Ks = Qs + AQ_HALVES;
    __half* Vs = Ks + 2 * AK_HALVES;

    const int tid  = threadIdx.x;
    const int wid  = tid >> 5;
    const int lane = tid & 31;
    const int g = lane >> 2;
    const int t = lane & 3;
    const int qrow0 = wid * 16;

    const int rowA  = lane & 15;
    const int koffA = (lane >> 4) * 8;
    const int rowB  = (lane & 7) + ((lane >> 4) << 3);
    const int koffB = ((lane >> 3) & 1) * 8;

    const int q0 = qt * ABM;
    const int jtmax = 2 * qt + 1;
    const __half* vtb = Vth + (size_t)(b * NKV_ + kvh) * HD_ * T_;
    const __half* qb  = QKVh + (size_t)(b * T_ + q0) * QKVN + h * HD_;
    const __half* kb  = QKVh + (size_t)(b * T_) * QKVN + C_ + kvh * HD_;

#pragma unroll
    for (int i = 0; i < 8; i++) {
        int v = i * 256 + tid;
        int r = v >> 4, c = v & 15;
        *(uint4*)(Qs + r * AH_QST + c * 8) = *(const uint4*)(qb + (size_t)r * QKVN + c * 8);
    }

    auto load_kv = [&](int jt, int buf) {
        const int j0 = jt * ABN;
        __half* ks = Ks + buf * AK_HALVES;
        __half* vs = Vs + buf * AV_HALVES;
#pragma unroll
        for (int i = 0; i < 4; i++) {
            int v = i * 256 + tid;
            int r = v >> 4, c = v & 15;
            cp_async16(ks + r * AH_QST + c * 8, kb + (size_t)(j0 + r) * QKVN + c * 8);
        }
#pragma unroll
        for (int i = 0; i < 4; i++) {
            int v = i * 256 + tid;
            int r = v >> 3, c = v & 7;
            cp_async16(vs + r * AH_VST + c * 8, vtb + (size_t)r * T_ + j0 + c * 8);
        }
    };

    float o[16][4];
#pragma unroll
    for (int nt = 0; nt < 16; nt++)
#pragma unroll
        for (int r = 0; r < 4; r++) o[nt][r] = 0.f;
    float m_lo = -1e30f, m_hi = -1e30f, l_lo = 0.f, l_hi = 0.f;

    load_kv(0, 0);
    CP_COMMIT();

    // scale folded with log2(e): softmax runs in exp2 domain
    const float scale = 0.08838834764831845f * 1.4426950408889634f;
    const int rl = qrow0 + g, rh = rl + 8;

    for (int jt = 0; jt <= jtmax; jt++) {
        const int cur = jt & 1;
        CP_WAIT(0);
        __syncthreads();
        if (jt < jtmax) {
            load_kv(jt + 1, cur ^ 1);
            CP_COMMIT();
        }

        const __half* ksf = Ks + cur * AK_HALVES;
        const __half* vsf = Vs + cur * AV_HALVES;

        // ---- S = Q K^T ----
        float s[8][4];
#pragma unroll
        for (int nt = 0; nt < 8; nt++)
#pragma unroll
            for (int r = 0; r < 4; r++) s[nt][r] = 0.f;

#pragma unroll
        for (int kk = 0; kk < HD_; kk += 16) {
            uint32_t af[4], bf[4][4];
            ldsm4(af, Qs + (qrow0 + rowA) * AH_QST + kk + koffA);
#pragma unroll
            for (int np = 0; np < 4; np++)
                ldsm4(bf[np], ksf + (np * 16 + rowB) * AH_QST + kk + koffB);
#pragma unroll
            for (int nt = 0; nt < 8; nt++)
                MMA_F16(s[nt], af, (&bf[nt >> 1][(nt & 1) * 2]));
        }

        // ---- scale (log2 domain) + mask + max ----
        const bool diag = (jt >= 2 * qt);
        float mxlo = -1e30f, mxhi = -1e30f;
#pragma unroll
        for (int nt = 0; nt < 8; nt++) {
            int gc0 = jt * ABN + nt * 8 + 2 * t;
            s[nt][0] *= scale; s[nt][1] *= scale;
            s[nt][2] *= scale; s[nt][3] *= scale;
            if (diag) {
                if (gc0     > q0 + rl) s[nt][0] = -1e30f;
                if (gc0 + 1 > q0 + rl) s[nt][1] = -1e30f;
                if (gc0     > q0 + rh) s[nt][2] = -1e30f;
                if (gc0 + 1 > q0 + rh) s[nt][3] = -1e30f;
            }
            mxlo = fmaxf(mxlo, fmaxf(s[nt][0], s[nt][1]));
            mxhi = fmaxf(mxhi, fmaxf(s[nt][2], s[nt][3]));
        }
        mxlo = fmaxf(mxlo, __shfl_xor_sync(0xffffffffu, mxlo, 1));
        mxlo = fmaxf(mxlo, __shfl_xor_sync(0xffffffffu, mxlo, 2));
        mxhi = fmaxf(mxhi, __shfl_xor_sync(0xffffffffu, mxhi, 1));
        mxhi = fmaxf(mxhi, __shfl_xor_sync(0xffffffffu, mxhi, 2));
        mxlo = fmaxf(mxlo, m_lo);
        mxhi = fmaxf(mxhi, m_hi);

        // ---- alpha + O rescale first (depends only on mx) ----
        float alo = ex2f(m_lo - mxlo);
        float ahi = ex2f(m_hi - mxhi);
        m_lo = mxlo;
        m_hi = mxhi;
#pragma unroll
        for (int nt = 0; nt < 16; nt++) {
            o[nt][0] *= alo; o[nt][1] *= alo;
            o[nt][2] *= ahi; o[nt][3] *= ahi;
        }

        // ---- exp (bare ex2) + pack P; partial sums in fp32 ----
        uint32_t ph[16];
        float sumlo = 0.f, sumhi = 0.f;
#pragma unroll
        for (int nt = 0; nt < 8; nt++) {
            float p0 = ex2f(s[nt][0] - mxlo);
            float p1 = ex2f(s[nt][1] - mxlo);
            float p2 = ex2f(s[nt][2] - mxhi);
            float p3 = ex2f(s[nt][3] - mxhi);
            __half2 plo = __floats2half2_rn(p0, p1);
            __half2 phi = __floats2half2_rn(p2, p3);
            sumlo += __low2float(plo) + __high2float(plo);
            sumhi += __low2float(phi) + __high2float(phi);
            ph[nt * 2]     = *(uint32_t*)&plo;
            ph[nt * 2 + 1] = *(uint32_t*)&phi;
        }

        // ---- O += P @ V (issue MMAs before the sum-reduction tail) ----
#pragma unroll
        for (int kk = 0; kk < ABN; kk += 16) {
            const int j = kk >> 4;
            uint32_t a[4] = { ph[4 * j], ph[4 * j + 1], ph[4 * j + 2], ph[4 * j + 3] };
            uint32_t bf[8][4];
#pragma unroll
            for (int np = 0; np < 8; np++)
                ldsm4(bf[np], vsf + (np * 16 + rowB) * AH_VST + kk + koffB);
#pragma unroll
            for (int nt = 0; nt < 16; nt++)
                MMA_F16(o[nt], a, (&bf[nt >> 1][(nt & 1) * 2]));
        }

        // ---- deferred sum reduction + l update (hides behind MMA) ----
        sumlo += __shfl_xor_sync(0xffffffffu, sumlo, 1);
        sumlo += __shfl_xor_sync(0xffffffffu, sumlo, 2);
        sumhi += __shfl_xor_sync(0xffffffffu, sumhi, 1);
        sumhi += __shfl_xor_sync(0xffffffffu, sumhi, 2);
        l_lo = l_lo * alo + sumlo;
        l_hi = l_hi * ahi + sumhi;
    }

    float inv_lo = 1.f / l_lo;
    float inv_hi = 1.f / l_hi;
    __half* dlo = Oh + (size_t)(b * T_ + q0 + rl) * C_ + h * HD_;
    __half* dhi = Oh + (size_t)(b * T_ + q0 + rh) * C_ + h * HD_;
#pragma unroll
    for (int nt = 0; nt < 16; nt++) {
        int col = nt * 8 + 2 * t;
        *(__half2*)(dlo + col) = __floats2half2_rn(o[nt][0] * inv_lo, o[nt][1] * inv_lo);
        *(__half2*)(dhi + col) = __floats2half2_rn(o[nt][2] * inv_hi, o[nt][3] * inv_hi);
    }
}

// ---------------- launch ------------------------------------------------------
extern "C" void kernel_launch(void* const* d_in, const int* in_sizes, int n_in,
                              void* d_out, int out_size) {
    const float* x  = (const float*)d_in[0];
    const float* Wq = (const float*)d_in[1];
    const float* Wk = (const float*)d_in[2];
    const float* Wv = (const float*)d_in[3];
    const float* Wo = (const float*)d_in[4];
    float* y = (float*)d_out;

    __half *wqkvh, *worh, *qkvh, *vth, *oh;
    float4* ropetab;
    cudaGetSymbolAddress((void**)&wqkvh, g_wqkvh);
    cudaGetSymbolAddress((void**)&worh,  g_worh);
    cudaGetSymbolAddress((void**)&qkvh,  g_qkvh);
    cudaGetSymbolAddress((void**)&vth,   g_vth);
    cudaGetSymbolAddress((void**)&oh,    g_oh);
    cudaGetSymbolAddress((void**)&ropetab, g_ropetab);

    cudaFuncSetAttribute(attn_h_kernel, cudaFuncAttributeMaxDynamicSharedMemorySize,
                         ATTH_SMEM_BYTES);
    cudaFuncSetAttribute((gemm_h<float, __half, true, 32>),
                         cudaFuncAttributeMaxDynamicSharedMemorySize, GEMM_SMEM(32));
    cudaFuncSetAttribute((gemm_h<__half, float, false, 64>),
                         cudaFuncAttributeMaxDynamicSharedMemorySize, GEMM_SMEM(64));

    // weight fp16 conversion + rope table (one launch)
    prep_kernel<<<(unsigned)((PREP_TOTAL + 255) / 256), 256>>>(Wq, Wk, Wv, Wo, ropetab);

    // fused QKV projection: fp32 x in; rope for q/k; transposed V to g_vth
    gemm_h<float, __half, true, 32><<<dim3(QKVN / HBN, M_ / HBM), 256, GEMM_SMEM(32)>>>(
        x, wqkvh, qkvh, vth, ropetab, M_, QKVN, C_);

    // attention (fp16 TC, FA2 register-P, occ 2, 1 barrier/iter)
    attn_h_kernel<<<dim3(T_ / ABM, NH_, B_), 256, ATTH_SMEM_BYTES>>>(qkvh, vth, oh);

    // output projection: fp16 in, fp32 out, K-chunk 64 (half the barriers)
    gemm_h<__half, float, false, 64><<<dim3(C_ / HBN, M_ / HBM), 256, GEMM_SMEM(64)>>>(
        oh, worh, y, nullptr, nullptr, M_, C_, C_);
}